// round 2
// baseline (speedup 1.0000x reference)
#include <cuda_runtime.h>
#include <cstdint>

typedef unsigned long long ull;

#define HB (1024*512)

// ---------------- scratch (static __device__, no allocations) ----------------
static __device__ float g_WhhT[4096u*1024u];      // [k][j] transposed W_hh
static __device__ float g_WfT [4096u*1024u];      // [k][j] fused W_hh + W_ih@W_out
static __device__ float g_WoutT[1024u*256u];      // [k][o]
static __device__ float g_b0[4096];               // b_ih+b_hh
static __device__ float g_bf[4096];               // b0 + W_ih@b_out
static __device__ float g_Hall[129ull*1024u*512u];// h_0..h_128, each [k][b]
static __device__ float g_c[2u*1024u*512u];       // c ping-pong, [k][b]

// ---------------- f32x2 helpers ----------------
__device__ __forceinline__ ull pack2(float x, float y) {
    ull d; asm("mov.b64 %0, {%1, %2};" : "=l"(d) : "f"(x), "f"(y)); return d;
}
__device__ __forceinline__ float2 unpack2(ull v) {
    float2 r; asm("mov.b64 {%0, %1}, %2;" : "=f"(r.x), "=f"(r.y) : "l"(v)); return r;
}
__device__ __forceinline__ void fma2(ull &c, ull a, ull b) {
    asm("fma.rn.f32x2 %0, %1, %2, %0;" : "+l"(c) : "l"(a), "l"(b));
}
__device__ __forceinline__ float sigm(float x) { return 1.0f / (1.0f + __expf(-x)); }

// ---------------- transpose MxN -> NxM into a selected global ----------------
__global__ void transpose_k(const float* __restrict__ in, int M, int N, int dst)
{
    __shared__ float s[32][33];
    float* out = (dst == 0) ? g_WhhT : (dst == 1) ? g_WoutT : g_Hall;
    int bx = blockIdx.x * 32;   // N offset
    int by = blockIdx.y * 32;   // M offset
    int tx = threadIdx.x, ty = threadIdx.y;
#pragma unroll
    for (int i = 0; i < 32; i += 8)
        s[ty + i][tx] = in[(size_t)(by + ty + i) * N + bx + tx];
    __syncthreads();
#pragma unroll
    for (int i = 0; i < 32; i += 8)
        out[(size_t)(bx + ty + i) * M + by + tx] = s[tx][ty + i];
}

// ---------------- biases: b0 = b_ih+b_hh ; bf = b0 + W_ih @ b_out ----------------
__global__ void prep_bias(const float* __restrict__ Wih,
                          const float* __restrict__ bih,
                          const float* __restrict__ bhh,
                          const float* __restrict__ bout)
{
    int j = blockIdx.x * 256 + threadIdx.x;    // 0..4095
    float s = bih[j] + bhh[j];
    g_b0[j] = s;
    float acc = 0.f;
#pragma unroll 8
    for (int o = 0; o < 256; o++) acc += Wih[(size_t)j * 256 + o] * bout[o];
    g_bf[j] = s + acc;
}

// ---------------- fused weight: WfT[k][j] = WhhT[k][j] + sum_o Wih[j][o]*Wout[o][k] ----
// grid: (4096/128, 1024/64), 256 threads. thread: 8 j (4 f32x2 pairs) x 4 k.
__global__ __launch_bounds__(256, 1) void prep_fuse(const float* __restrict__ Wih,
                                                    const float* __restrict__ Wout)
{
    __shared__ float sA[16][130];   // [o][j]  (padded: bank + 8B align)
    __shared__ float sB[16][64];    // [o][k]
    const int tid = threadIdx.x;
    const int j0 = blockIdx.x * 128;
    const int k0 = blockIdx.y * 64;
    const int jx = tid & 15;        // 16 groups of 8 j
    const int ky = tid >> 4;        // 16 groups of 4 k

    ull acc[4][4];
#pragma unroll
    for (int i = 0; i < 4; i++) {
        const ull* src = (const ull*)&g_WhhT[(size_t)(k0 + ky * 4 + i) * 4096 + j0 + jx * 8];
#pragma unroll
        for (int p = 0; p < 4; p++) acc[i][p] = src[p];
    }

    for (int ot = 0; ot < 256; ot += 16) {
#pragma unroll
        for (int r = 0; r < 8; r++) {
            int idx = r * 256 + tid; int j = idx >> 4, oo = idx & 15;
            sA[oo][j] = Wih[(size_t)(j0 + j) * 256 + ot + oo];
        }
#pragma unroll
        for (int r = 0; r < 4; r++) {
            int idx = r * 256 + tid; int oo = idx >> 6, k = idx & 63;
            sB[oo][k] = Wout[(size_t)(ot + oo) * 1024 + k0 + k];
        }
        __syncthreads();
#pragma unroll
        for (int oo = 0; oo < 16; oo++) {
            ull w2[4];
#pragma unroll
            for (int p = 0; p < 4; p++) w2[p] = *(const ull*)&sA[oo][jx * 8 + 2 * p];
#pragma unroll
            for (int i = 0; i < 4; i++) {
                float a = sB[oo][ky * 4 + i];
                ull a2 = pack2(a, a);
#pragma unroll
                for (int p = 0; p < 4; p++) fma2(acc[i][p], w2[p], a2);
            }
        }
        __syncthreads();
    }
#pragma unroll
    for (int i = 0; i < 4; i++) {
        ull* dst = (ull*)&g_WfT[(size_t)(k0 + ky * 4 + i) * 4096 + j0 + jx * 8];
#pragma unroll
        for (int p = 0; p < 4; p++) dst[p] = acc[i][p];
    }
}

// ---------------- one LSTM step: gates = h @ W^T + bias, cell update ----------------
// W layout [k][j] (j = gate*1024 + cell). h/c layout [k][b].
// grid (4, 32): 128 batch x 32 cells per CTA. 256 threads:
//   cell = tid&31 (1 cell), bg = tid>>5 (16 batches = 8 f32x2 pairs). 4 gates.
__global__ __launch_bounds__(256, 1) void lstm_step(int t)
{
    __shared__ float sh[16][128];   // [k][b]
    __shared__ float sw[16][128];   // [k][g*32+c]

    const float* W    = (t == 1) ? g_WhhT : g_WfT;
    const float* bias = (t == 1) ? g_b0   : g_bf;
    const float* h_in = g_Hall + (size_t)(t - 1) * HB;
    float*       h_out= g_Hall + (size_t)t * HB;
    const float* c_in = g_c + (size_t)((t - 1) & 1) * HB;
    float*       c_out= g_c + (size_t)(t & 1) * HB;
    const int first = (t == 1);

    const int tid  = threadIdx.x;
    const int b0   = blockIdx.x * 128;
    const int c0   = blockIdx.y * 32;
    const int cell = tid & 31;
    const int bg   = tid >> 5;
    const int bbase= bg * 16;

    ull acc[4][8];
#pragma unroll
    for (int g = 0; g < 4; g++) {
        float bv = bias[g * 1024 + c0 + cell];
        ull b2 = pack2(bv, bv);
#pragma unroll
        for (int i = 0; i < 8; i++) acc[g][i] = b2;
    }

    const float4* h4 = (const float4*)h_in;   // row = 128 float4
    const float4* W4 = (const float4*)W;      // row = 1024 float4

    // register-staged prefetch (2 float4 pairs per thread per tile)
    float4 ph[2], pw[2];
#pragma unroll
    for (int r = 0; r < 2; r++) {
        int idx = r * 256 + tid; int kk = idx >> 5, q = idx & 31;
        ph[r] = h4[(size_t)kk * 128 + (b0 >> 2) + q];
        int g = q >> 3, c4 = q & 7;
        pw[r] = W4[(size_t)kk * 1024 + g * 256 + (c0 >> 2) + c4];
    }

    for (int k0 = 0; k0 < 1024; k0 += 16) {
#pragma unroll
        for (int r = 0; r < 2; r++) {
            int idx = r * 256 + tid; int kk = idx >> 5, q = idx & 31;
            ((float4*)sh)[kk * 32 + q] = ph[r];
            ((float4*)sw)[kk * 32 + q] = pw[r];
        }
        __syncthreads();
        if (k0 + 16 < 1024) {
#pragma unroll
            for (int r = 0; r < 2; r++) {
                int idx = r * 256 + tid; int kk = idx >> 5, q = idx & 31;
                ph[r] = h4[(size_t)(k0 + 16 + kk) * 128 + (b0 >> 2) + q];
                int g = q >> 3, c4 = q & 7;
                pw[r] = W4[(size_t)(k0 + 16 + kk) * 1024 + g * 256 + (c0 >> 2) + c4];
            }
        }
#pragma unroll
        for (int kk = 0; kk < 16; kk++) {
            const ulonglong2* ap = (const ulonglong2*)&sh[kk][bbase];
            ulonglong2 a01 = ap[0], a23 = ap[1], a45 = ap[2], a67 = ap[3];
            ull a[8] = {a01.x, a01.y, a23.x, a23.y, a45.x, a45.y, a67.x, a67.y};
            ull w2[4];
#pragma unroll
            for (int g = 0; g < 4; g++) {
                float w = sw[kk][g * 32 + cell];
                w2[g] = pack2(w, w);
            }
#pragma unroll
            for (int g = 0; g < 4; g++)
#pragma unroll
                for (int i = 0; i < 8; i++) fma2(acc[g][i], a[i], w2[g]);
        }
        __syncthreads();
    }

    // ---- LSTM cell update ----
    const int jc = c0 + cell;
#pragma unroll
    for (int i = 0; i < 8; i++) {
        float2 gi = unpack2(acc[0][i]);
        float2 gf = unpack2(acc[1][i]);
        float2 gg = unpack2(acc[2][i]);
        float2 go = unpack2(acc[3][i]);
        int bb = b0 + bbase + 2 * i;
        float cold0 = first ? 0.f : c_in[(size_t)jc * 512 + bb];
        float cold1 = first ? 0.f : c_in[(size_t)jc * 512 + bb + 1];
        float cn0 = sigm(gf.x) * cold0 + sigm(gi.x) * tanhf(gg.x);
        float cn1 = sigm(gf.y) * cold1 + sigm(gi.y) * tanhf(gg.y);
        float hn0 = sigm(go.x) * tanhf(cn0);
        float hn1 = sigm(go.y) * tanhf(cn1);
        *(float2*)&c_out[(size_t)jc * 512 + bb] = make_float2(cn0, cn1);
        *(float2*)&h_out[(size_t)jc * 512 + bb] = make_float2(hn0, hn1);
    }
}

// ---------------- batched output GEMM: out[b][t][o] = h_{t+1} @ W_out^T + b_out ------
// grid (4, 2, 128): 128 b x 128 o per CTA per t. 256 threads: 8 b x 8 o (pairs over o).
__global__ __launch_bounds__(256, 1) void out_gemm(const float* __restrict__ bout,
                                                   float* __restrict__ out)
{
    __shared__ float sH[16][128];   // [k][b]
    __shared__ float sW[16][128];   // [k][o]
    const int tid = threadIdx.x;
    const int t  = blockIdx.z;
    const int b0 = blockIdx.x * 128;
    const int o0 = blockIdx.y * 128;
    const int ox = tid & 15;
    const int by = tid >> 4;
    const float* Ht = g_Hall + (size_t)(t + 1) * HB;

    ull acc[8][4];
#pragma unroll
    for (int p = 0; p < 4; p++) {
        ull b2 = *(const ull*)&bout[o0 + ox * 8 + 2 * p];
#pragma unroll
        for (int i = 0; i < 8; i++) acc[i][p] = b2;
    }

    const float4* H4 = (const float4*)Ht;       // row = 128 float4
    const float4* W4 = (const float4*)g_WoutT;  // row = 64 float4

    float4 pa[2], pb[2];
#pragma unroll
    for (int r = 0; r < 2; r++) {
        int idx = r * 256 + tid; int kk = idx >> 5, q = idx & 31;
        pa[r] = H4[(size_t)kk * 128 + (b0 >> 2) + q];
        pb[r] = W4[(size_t)kk * 64 + (o0 >> 2) + q];
    }

    for (int k0 = 0; k0 < 1024; k0 += 16) {
#pragma unroll
        for (int r = 0; r < 2; r++) {
            int idx = r * 256 + tid; int kk = idx >> 5, q = idx & 31;
            ((float4*)sH)[kk * 32 + q] = pa[r];
            ((float4*)sW)[kk * 32 + q] = pb[r];
        }
        __syncthreads();
        if (k0 + 16 < 1024) {
#pragma unroll
            for (int r = 0; r < 2; r++) {
                int idx = r * 256 + tid; int kk = idx >> 5, q = idx & 31;
                pa[r] = H4[(size_t)(k0 + 16 + kk) * 128 + (b0 >> 2) + q];
                pb[r] = W4[(size_t)(k0 + 16 + kk) * 64 + (o0 >> 2) + q];
            }
        }
#pragma unroll
        for (int kk = 0; kk < 16; kk++) {
            float4 a0 = *(const float4*)&sH[kk][by * 8];
            float4 a1 = *(const float4*)&sH[kk][by * 8 + 4];
            ulonglong2 wv0 = *(const ulonglong2*)&sW[kk][ox * 8];
            ulonglong2 wv1 = *(const ulonglong2*)&sW[kk][ox * 8 + 4];
            ull w2[4] = {wv0.x, wv0.y, wv1.x, wv1.y};
            float as[8] = {a0.x, a0.y, a0.z, a0.w, a1.x, a1.y, a1.z, a1.w};
#pragma unroll
            for (int i = 0; i < 8; i++) {
                ull a2 = pack2(as[i], as[i]);
#pragma unroll
                for (int p = 0; p < 4; p++) fma2(acc[i][p], w2[p], a2);
            }
        }
        __syncthreads();
    }

#pragma unroll
    for (int i = 0; i < 8; i++) {
        size_t base = (size_t)(b0 + by * 8 + i) * (128 * 256) + (size_t)t * 256 + o0 + ox * 8;
        ull* op = (ull*)(out + base);
#pragma unroll
        for (int p = 0; p < 4; p++) op[p] = acc[i][p];
    }
}

// ---------------- launch ----------------
extern "C" void kernel_launch(void* const* d_in, const int* in_sizes, int n_in,
                              void* d_out, int out_size)
{
    const float *enc = nullptr, *Wih = nullptr, *Whh = nullptr;
    const float *bih = nullptr, *bhh = nullptr, *Wout = nullptr, *bout = nullptr;
    for (int i = 0; i < n_in; i++) {
        int s = in_sizes[i];
        if      (s == 512 * 1024)  enc  = (const float*)d_in[i];
        else if (s == 4096 * 256)  Wih  = (const float*)d_in[i];
        else if (s == 4096 * 1024) Whh  = (const float*)d_in[i];
        else if (s == 4096)        { if (!bih) bih = (const float*)d_in[i]; else bhh = (const float*)d_in[i]; }
        else if (s == 256 * 1024)  Wout = (const float*)d_in[i];
        else if (s == 256)         bout = (const float*)d_in[i];
        // size-1 target_length ignored (T=128 compile-time)
    }
    if (!enc || !Wih || !Whh || !bih || !bhh || !Wout || !bout) return;

    dim3 tb(32, 8);
    transpose_k<<<dim3(1024 / 32, 4096 / 32), tb>>>(Whh, 4096, 1024, 0);   // -> g_WhhT
    transpose_k<<<dim3(1024 / 32,  256 / 32), tb>>>(Wout, 256, 1024, 1);   // -> g_WoutT
    transpose_k<<<dim3(1024 / 32,  512 / 32), tb>>>(enc,  512, 1024, 2);   // -> g_Hall[0]
    prep_bias<<<16, 256>>>(Wih, bih, bhh, bout);
    prep_fuse<<<dim3(32, 16), 256>>>(Wih, Wout);

    for (int t = 1; t <= 128; t++)
        lstm_step<<<dim3(4, 32), 256>>>(t);

    out_gemm<<<dim3(4, 2, 128), 256>>>(bout, (float*)d_out);
    (void)out_size;
}

// round 4
// speedup vs baseline: 2.4885x; 2.4885x over previous
#include <cuda_runtime.h>
#include <cuda_bf16.h>
#include <cstdint>

typedef unsigned long long ull;
typedef unsigned int u32;

#define HB (1024*512)

// ---------------- scratch (static __device__, no allocations) ----------------
static __device__ float g_WhhT[4096u*1024u];      // [k][j]
static __device__ float g_WfT [4096u*1024u];      // [k][j] fused W_hh + W_ih@W_out
static __device__ float g_WoutT[1024u*256u];      // [k][o]
static __device__ float g_b0[4096];               // b_ih+b_hh (orig j layout)
static __device__ float g_bf[4096];               // + W_ih@b_out
static __device__ float g_Hall[129ull*HB];        // h_1..h_128, [k][b]
static __device__ float g_c[2u*HB];               // c ping-pong, [k][b]
// pre-swizzled bf16 operand tiles (Swizzle<3,4,3> on 128B rows)
// weights: [src][cellT(16)][chunk(16)][part hi/lo][256n x 64k]
static __device__ __align__(256) __nv_bfloat16 g_wbf[2][16][16][2][16384];
// hidden A: [buf][mT(8)][chunk(16)][part][64m x 64k]
static __device__ __align__(256) __nv_bfloat16 g_hbf[2][8][16][2][4096];

// ---------------- helpers ----------------
__device__ __forceinline__ ull pack2(float x, float y) {
    ull d; asm("mov.b64 %0, {%1, %2};" : "=l"(d) : "f"(x), "f"(y)); return d;
}
__device__ __forceinline__ void fma2(ull &c, ull a, ull b) {
    asm("fma.rn.f32x2 %0, %1, %2, %0;" : "+l"(c) : "l"(a), "l"(b));
}
__device__ __forceinline__ float sigm(float x) { return 1.0f / (1.0f + __expf(-x)); }
__device__ __forceinline__ u32 swz(u32 x) { return x ^ ((x >> 3) & 0x70); }
__device__ __forceinline__ u32 smem_u32(const void* p) {
    u32 a; asm("{ .reg .u64 t; cvta.to.shared.u64 t, %1; cvt.u32.u64 %0, t; }" : "=r"(a) : "l"(p));
    return a;
}
__device__ __forceinline__ void cpa16(u32 dst, const void* src) {
    asm volatile("cp.async.cg.shared.global [%0], [%1], 16;" :: "r"(dst), "l"(src));
}
#define CP_COMMIT() asm volatile("cp.async.commit_group;" ::: "memory")
#define CP_WAIT1()  asm volatile("cp.async.wait_group 1;" ::: "memory")

__device__ __forceinline__ void ldsm4(u32* r, u32 addr) {
    asm volatile("ldmatrix.sync.aligned.m8n8.x4.shared.b16 {%0,%1,%2,%3}, [%4];"
                 : "=r"(r[0]), "=r"(r[1]), "=r"(r[2]), "=r"(r[3]) : "r"(addr));
}
__device__ __forceinline__ void mma_bf16(float* d, const u32* a, const u32* b) {
    asm volatile("mma.sync.aligned.m16n8k16.row.col.f32.bf16.bf16.f32 "
                 "{%0,%1,%2,%3}, {%4,%5,%6,%7}, {%8,%9}, {%0,%1,%2,%3};"
                 : "+f"(d[0]), "+f"(d[1]), "+f"(d[2]), "+f"(d[3])
                 : "r"(a[0]), "r"(a[1]), "r"(a[2]), "r"(a[3]), "r"(b[0]), "r"(b[1]));
}

// ---------------- transpose MxN -> NxM into a selected global ----------------
__global__ void transpose_k(const float* __restrict__ in, int M, int N, int dst)
{
    __shared__ float s[32][33];
    float* out = (dst == 0) ? g_WhhT : g_WoutT;
    int bx = blockIdx.x * 32, by = blockIdx.y * 32;
    int tx = threadIdx.x, ty = threadIdx.y;
#pragma unroll
    for (int i = 0; i < 32; i += 8)
        s[ty + i][tx] = in[(size_t)(by + ty + i) * N + bx + tx];
    __syncthreads();
#pragma unroll
    for (int i = 0; i < 32; i += 8)
        out[(size_t)(bx + ty + i) * M + by + tx] = s[tx][ty + i];
}

// ---------------- biases ----------------
__global__ void prep_bias(const float* __restrict__ Wih,
                          const float* __restrict__ bih,
                          const float* __restrict__ bhh,
                          const float* __restrict__ bout)
{
    int j = blockIdx.x * 256 + threadIdx.x;    // 0..4095
    float s = bih[j] + bhh[j];
    g_b0[j] = s;
    float acc = 0.f;
#pragma unroll 8
    for (int o = 0; o < 256; o++) acc += Wih[(size_t)j * 256 + o] * bout[o];
    g_bf[j] = s + acc;
}

// ---------------- fused weight: WfT[k][j] = WhhT[k][j] + sum_o Wih[j][o]*Wout[o][k] ----
__global__ __launch_bounds__(256, 1) void prep_fuse(const float* __restrict__ Wih,
                                                    const float* __restrict__ Wout)
{
    __shared__ float sA[16][130];
    __shared__ float sB[16][64];
    const int tid = threadIdx.x;
    const int j0 = blockIdx.x * 128;
    const int k0 = blockIdx.y * 64;
    const int jx = tid & 15;
    const int ky = tid >> 4;

    ull acc[4][4];
#pragma unroll
    for (int i = 0; i < 4; i++) {
        const ull* src = (const ull*)&g_WhhT[(size_t)(k0 + ky * 4 + i) * 4096 + j0 + jx * 8];
#pragma unroll
        for (int p = 0; p < 4; p++) acc[i][p] = src[p];
    }
    for (int ot = 0; ot < 256; ot += 16) {
#pragma unroll
        for (int r = 0; r < 8; r++) {
            int idx = r * 256 + tid; int j = idx >> 4, oo = idx & 15;
            sA[oo][j] = Wih[(size_t)(j0 + j) * 256 + ot + oo];
        }
#pragma unroll
        for (int r = 0; r < 4; r++) {
            int idx = r * 256 + tid; int oo = idx >> 6, k = idx & 63;
            sB[oo][k] = Wout[(size_t)(ot + oo) * 1024 + k0 + k];
        }
        __syncthreads();
#pragma unroll
        for (int oo = 0; oo < 16; oo++) {
            ull w2[4];
#pragma unroll
            for (int p = 0; p < 4; p++) w2[p] = *(const ull*)&sA[oo][jx * 8 + 2 * p];
#pragma unroll
            for (int i = 0; i < 4; i++) {
                float a = sB[oo][ky * 4 + i];
                ull a2 = pack2(a, a);
#pragma unroll
                for (int p = 0; p < 4; p++) fma2(acc[i][p], w2[p], a2);
            }
        }
        __syncthreads();
    }
#pragma unroll
    for (int i = 0; i < 4; i++) {
        ull* dst = (ull*)&g_WfT[(size_t)(k0 + ky * 4 + i) * 4096 + j0 + jx * 8];
#pragma unroll
        for (int p = 0; p < 4; p++) dst[p] = acc[i][p];
    }
}

// ---------------- weights -> bf16 hi/lo, gate-paired reorder, pre-swizzled ----------------
// B tile row n (0..255): n<128: cell=cellT*64+(n>>1), gate=n&1 (i/f)
//                        n>=128: m=n-128, cell=cellT*64+(m>>1), gate=2+(m&1) (g/o)
__global__ void conv_w()
{
    int chunk = blockIdx.x, cellT = blockIdx.y, src = blockIdx.z;
    const float* W = src ? g_WfT : g_WhhT;
    char* th = (char*)&g_wbf[src][cellT][chunk][0][0];
    char* tl = th + 32768;
    int n = threadIdx.x;
    int m = (n < 128) ? n : (n - 128);
    int gate = ((n < 128) ? 0 : 2) + (m & 1);
    size_t j = (size_t)gate * 1024 + cellT * 64 + (m >> 1);
#pragma unroll 4
    for (int kk = 0; kk < 64; kk++) {
        float v = W[(size_t)(chunk * 64 + kk) * 4096 + j];
        __nv_bfloat16 h = __float2bfloat16(v);
        __nv_bfloat16 l = __float2bfloat16(v - __bfloat162float(h));
        u32 off = swz((u32)(n * 128 + kk * 2));
        *(__nv_bfloat16*)(th + off) = h;
        *(__nv_bfloat16*)(tl + off) = l;
    }
}

// ---------------- h0 (= encoder_hidden, row-major [b][k]) -> bf16 A tiles, buf 0 ----------
__global__ void conv_h0(const float* __restrict__ enc)
{
    int chunk = blockIdx.x, mT = blockIdx.y;
    char* th = (char*)&g_hbf[0][mT][chunk][0][0];
    char* tl = th + 8192;
#pragma unroll
    for (int i = 0; i < 16; i++) {
        int e = i * 256 + threadIdx.x;  // 0..4095
        int m = e >> 6, kk = e & 63;
        float v = enc[(size_t)(mT * 64 + m) * 1024 + chunk * 64 + kk];
        __nv_bfloat16 h = __float2bfloat16(v);
        __nv_bfloat16 l = __float2bfloat16(v - __bfloat162float(h));
        u32 off = swz((u32)(m * 128 + kk * 2));
        *(__nv_bfloat16*)(th + off) = h;
        *(__nv_bfloat16*)(tl + off) = l;
    }
}

// ---------------- mma.sync LSTM step ----------------
// CTA = 64 batch x 256 gate-cols (64 cells x {i,f | g,o}). K=1024, 16 chunks of 64.
// 3 split-bf16 passes -> fp32 register accumulators. Epilogue = LSTM cell update.
#define STAGE 81920
#define SMEM_TOTAL (2*STAGE + 1024)

__global__ __launch_bounds__(256, 1) void lstm_mma(int t)
{
    extern __shared__ char smem[];
    const u32 sb = (smem_u32(smem) + 1023) & ~1023u;
    const int tid = threadIdx.x, lane = tid & 31, w = tid >> 5;
    const int mT = blockIdx.x;      // 8
    const int cellT = blockIdx.y;   // 16
    const int buf = (t - 1) & 1;
    const int ws = (t == 1) ? 0 : 1;
    const int first = (t == 1);

    const char* srcA = (const char*)&g_hbf[buf][mT][0][0][0];   // chunk stride 16384B
    const char* srcB = (const char*)&g_wbf[ws][cellT][0][0][0]; // chunk stride 65536B

    // per-lane ldmatrix address components
    const int aRow = ((lane >> 3) & 1) * 8 + (lane & 7);
    const int aKh  = lane >> 4;
    const int bRow = (lane >> 4) * 8 + (lane & 7);
    const int bKh  = (lane >> 3) & 1;
    const int nIF = w * 16;
    const int nGO = 128 + w * 16;

    float dIF[4][2][4], dGO[4][2][4];
#pragma unroll
    for (int mi = 0; mi < 4; mi++)
#pragma unroll
        for (int nj = 0; nj < 2; nj++)
#pragma unroll
            for (int q = 0; q < 4; q++) { dIF[mi][nj][q] = 0.f; dGO[mi][nj][q] = 0.f; }

    // prologue: load chunks 0,1
#pragma unroll
    for (int pc = 0; pc < 2; pc++) {
        u32 stg = sb + pc * STAGE;
        const char* sA = srcA + (size_t)pc * 16384;
        const char* sB = srcB + (size_t)pc * 65536;
#pragma unroll
        for (int r = 0; r < 20; r++) {
            int idx = r * 256 + tid;
            if (idx < 1024) cpa16(stg + idx * 16, sA + (size_t)idx * 16);
            else            cpa16(stg + 16384 + (idx - 1024) * 16, sB + (size_t)(idx - 1024) * 16);
        }
        CP_COMMIT();
    }

    for (int c = 0; c < 16; c++) {
        int s = c & 1;
        CP_WAIT1();
        __syncthreads();
        u32 stgA = sb + s * STAGE;
        u32 stgB = stgA + 16384;
#pragma unroll
        for (int k16 = 0; k16 < 4; k16++) {
            u32 aH[4][4], aL[4][4];
#pragma unroll
            for (int mi = 0; mi < 4; mi++) {
                u32 off = swz((u32)((mi * 16 + aRow) * 128 + (k16 * 2 + aKh) * 16));
                ldsm4(aH[mi], stgA + off);
                ldsm4(aL[mi], stgA + 8192 + off);
            }
            u32 bHif[4], bLif[4], bHgo[4], bLgo[4];
            {
                u32 offIF = swz((u32)((nIF + bRow) * 128 + (k16 * 2 + bKh) * 16));
                u32 offGO = swz((u32)((nGO + bRow) * 128 + (k16 * 2 + bKh) * 16));
                ldsm4(bHif, stgB + offIF);
                ldsm4(bLif, stgB + 32768 + offIF);
                ldsm4(bHgo, stgB + offGO);
                ldsm4(bLgo, stgB + 32768 + offGO);
            }
#pragma unroll
            for (int mi = 0; mi < 4; mi++)
#pragma unroll
                for (int nj = 0; nj < 2; nj++) {
                    mma_bf16(dIF[mi][nj], aH[mi], &bHif[nj * 2]);
                    mma_bf16(dIF[mi][nj], aH[mi], &bLif[nj * 2]);
                    mma_bf16(dIF[mi][nj], aL[mi], &bHif[nj * 2]);
                    mma_bf16(dGO[mi][nj], aH[mi], &bHgo[nj * 2]);
                    mma_bf16(dGO[mi][nj], aH[mi], &bLgo[nj * 2]);
                    mma_bf16(dGO[mi][nj], aL[mi], &bHgo[nj * 2]);
                }
        }
        __syncthreads();
        if (c + 2 < 16) {
            u32 stg = sb + s * STAGE;
            const char* sA = srcA + (size_t)(c + 2) * 16384;
            const char* sB = srcB + (size_t)(c + 2) * 65536;
#pragma unroll
            for (int r = 0; r < 20; r++) {
                int idx = r * 256 + tid;
                if (idx < 1024) cpa16(stg + idx * 16, sA + (size_t)idx * 16);
                else            cpa16(stg + 16384 + (idx - 1024) * 16, sB + (size_t)(idx - 1024) * 16);
            }
        }
        CP_COMMIT();
    }

    // ---- epilogue: LSTM cell update + next-step A tile emit ----
    const float* bias = first ? g_b0 : g_bf;
    const float* c_in = g_c + (size_t)((t - 1) & 1) * HB;
    float* c_out = g_c + (size_t)(t & 1) * HB;
    float* h_out = g_Hall + (size_t)t * HB;
    char* dA = (char*)&g_hbf[t & 1][mT][cellT][0][0];   // hi at +0, lo at +8192

#pragma unroll
    for (int mi = 0; mi < 4; mi++)
#pragma unroll
        for (int rh = 0; rh < 2; rh++) {
            int b = mT * 64 + mi * 16 + (lane >> 2) + rh * 8;
#pragma unroll
            for (int nj = 0; nj < 2; nj++) {
                int cl = w * 8 + nj * 4 + (lane & 3);    // local cell 0..63
                int cell = cellT * 64 + cl;
                float gi = dIF[mi][nj][rh * 2 + 0] + bias[cell];
                float gf = dIF[mi][nj][rh * 2 + 1] + bias[1024 + cell];
                float gg = dGO[mi][nj][rh * 2 + 0] + bias[2048 + cell];
                float go = dGO[mi][nj][rh * 2 + 1] + bias[3072 + cell];
                float cold = first ? 0.f : c_in[(size_t)cell * 512 + b];
                float cn = sigm(gf) * cold + sigm(gi) * tanhf(gg);
                float hn = sigm(go) * tanhf(cn);
                c_out[(size_t)cell * 512 + b] = cn;
                h_out[(size_t)cell * 512 + b] = hn;
                __nv_bfloat16 hh = __float2bfloat16(hn);
                __nv_bfloat16 hl = __float2bfloat16(hn - __bfloat162float(hh));
                u32 off = swz((u32)((b & 63) * 128 + cl * 2));
                *(__nv_bfloat16*)(dA + off) = hh;
                *(__nv_bfloat16*)(dA + 8192 + off) = hl;
            }
        }
}

// ---------------- batched output GEMM: out[b][t][o] = h_{t+1} @ W_out^T + b_out ------
__global__ __launch_bounds__(256, 1) void out_gemm(const float* __restrict__ bout,
                                                   float* __restrict__ out)
{
    __shared__ float sH[16][128];
    __shared__ float sW[16][128];
    const int tid = threadIdx.x;
    const int t  = blockIdx.z;
    const int b0 = blockIdx.x * 128;
    const int o0 = blockIdx.y * 128;
    const int ox = tid & 15;
    const int by = tid >> 4;
    const float* Ht = g_Hall + (size_t)(t + 1) * HB;

    ull acc[8][4];
#pragma unroll
    for (int p = 0; p < 4; p++) {
        ull b2 = *(const ull*)&bout[o0 + ox * 8 + 2 * p];
#pragma unroll
        for (int i = 0; i < 8; i++) acc[i][p] = b2;
    }
    const float4* H4 = (const float4*)Ht;
    const float4* W4 = (const float4*)g_WoutT;

    float4 pa[2], pb[2];
#pragma unroll
    for (int r = 0; r < 2; r++) {
        int idx = r * 256 + tid; int kk = idx >> 5, q = idx & 31;
        pa[r] = H4[(size_t)kk * 128 + (b0 >> 2) + q];
        pb[r] = W4[(size_t)kk * 64 + (o0 >> 2) + q];
    }
    for (int k0 = 0; k0 < 1024; k0 += 16) {
#pragma unroll
        for (int r = 0; r < 2; r++) {
            int idx = r * 256 + tid; int kk = idx >> 5, q = idx & 31;
            ((float4*)sH)[kk * 32 + q] = pa[r];
            ((float4*)sW)[kk * 32 + q] = pb[r];
        }
        __syncthreads();
        if (k0 + 16 < 1024) {
#pragma unroll
            for (int r = 0; r < 2; r++) {
                int idx = r * 256 + tid; int kk = idx >> 5, q = idx & 31;
                pa[r] = H4[(size_t)(k0 + 16 + kk) * 128 + (b0 >> 2) + q];
                pb[r] = W4[(size_t)(k0 + 16 + kk) * 64 + (o0 >> 2) + q];
            }
        }
#pragma unroll
        for (int kk = 0; kk < 16; kk++) {
            float4 a0 = *(const float4*)&sH[kk][by * 8];
            float4 a1 = *(const float4*)&sH[kk][by * 8 + 4];
            ulonglong2 wv0 = *(const ulonglong2*)&sW[kk][ox * 8];
            ulonglong2 wv1 = *(const ulonglong2*)&sW[kk][ox * 8 + 4];
            ull w2[4] = {wv0.x, wv0.y, wv1.x, wv1.y};
            float as[8] = {a0.x, a0.y, a0.z, a0.w, a1.x, a1.y, a1.z, a1.w};
#pragma unroll
            for (int i = 0; i < 8; i++) {
                ull a2 = pack2(as[i], as[i]);
#pragma unroll
                for (int p = 0; p < 4; p++) fma2(acc[i][p], w2[p], a2);
            }
        }
        __syncthreads();
    }
#pragma unroll
    for (int i = 0; i < 8; i++) {
        size_t base = (size_t)(b0 + by * 8 + i) * (128 * 256) + (size_t)t * 256 + o0 + ox * 8;
        ull* op = (ull*)(out + base);
#pragma unroll
        for (int p = 0; p < 4; p++) op[p] = acc[i][p];
    }
}

// ---------------- launch ----------------
extern "C" void kernel_launch(void* const* d_in, const int* in_sizes, int n_in,
                              void* d_out, int out_size)
{
    const float *enc = nullptr, *Wih = nullptr, *Whh = nullptr;
    const float *bih = nullptr, *bhh = nullptr, *Wout = nullptr, *bout = nullptr;
    for (int i = 0; i < n_in; i++) {
        int s = in_sizes[i];
        if      (s == 512 * 1024)  enc  = (const float*)d_in[i];
        else if (s == 4096 * 256)  Wih  = (const float*)d_in[i];
        else if (s == 4096 * 1024) Whh  = (const float*)d_in[i];
        else if (s == 4096)        { if (!bih) bih = (const float*)d_in[i]; else bhh = (const float*)d_in[i]; }
        else if (s == 256 * 1024)  Wout = (const float*)d_in[i];
        else if (s == 256)         bout = (const float*)d_in[i];
    }
    if (!enc || !Wih || !Whh || !bih || !bhh || !Wout || !bout) return;

    static int attr_done = 0;
    cudaFuncSetAttribute(lstm_mma, cudaFuncAttributeMaxDynamicSharedMemorySize, SMEM_TOTAL);
    (void)attr_done;

    dim3 tb(32, 8);
    transpose_k<<<dim3(1024 / 32, 4096 / 32), tb>>>(Whh, 4096, 1024, 0);   // -> g_WhhT
    transpose_k<<<dim3(1024 / 32,  256 / 32), tb>>>(Wout, 256, 1024, 1);   // -> g_WoutT
    prep_bias<<<16, 256>>>(Wih, bih, bhh, bout);
    prep_fuse<<<dim3(32, 16), 256>>>(Wih, Wout);
    conv_w<<<dim3(16, 16, 2), 256>>>();
    conv_h0<<<dim3(16, 8), 256>>>(enc);

    for (int t = 1; t <= 128; t++)
        lstm_mma<<<dim3(8, 16), 256, SMEM_TOTAL>>>(t);

    out_gemm<<<dim3(4, 2, 128), 256>>>(bout, (float*)d_out);
    (void)out_size;
}

// round 5
// speedup vs baseline: 2.9631x; 1.1907x over previous
#include <cuda_runtime.h>
#include <cuda_bf16.h>
#include <cstdint>

typedef unsigned long long ull;
typedef unsigned int u32;

#define HB (1024*512)

// ---------------- scratch (static __device__, no allocations) ----------------
static __device__ float g_b0[4096];               // b_ih+b_hh
static __device__ float g_bf[4096];               // + W_ih@b_out
static __device__ float g_c[2u*HB];               // c ping-pong, [cell][b]
// weight tiles, gate-paired rows, SW128 pre-swizzled: [src][nT 32][chunk 16][part 2][128x64]
static __device__ __align__(256) __nv_bfloat16 g_wbf[2][32][16][2][8192];
// hidden tiles: [t 0..128][mT 4][chunk 16][part 2][128x64]
static __device__ __align__(256) __nv_bfloat16 g_hbf[129][4][16][2][8192];
// output-weight tiles: [nOT 2][chunk 16][part 2][128x64]
static __device__ __align__(256) __nv_bfloat16 g_obf[2][16][2][8192];
// prep-GEMM operands: Wih gate-paired [nT][oc 4][part][128x64]; WoutT [kc 16][oc 4][part][64x64]
static __device__ __align__(256) __nv_bfloat16 g_pA[32][4][2][8192];
static __device__ __align__(256) __nv_bfloat16 g_pB[16][4][2][4096];

// ---------------- helpers ----------------
__device__ __forceinline__ float sigm(float x) { return 1.0f / (1.0f + __expf(-x)); }
__device__ __forceinline__ u32 swz(u32 x) { return x ^ ((x >> 3) & 0x70); }
__device__ __forceinline__ u32 smem_u32(const void* p) {
    u32 a; asm("{ .reg .u64 t; cvta.to.shared.u64 t, %1; cvt.u32.u64 %0, t; }" : "=r"(a) : "l"(p));
    return a;
}
__device__ __forceinline__ void cpa16(u32 dst, const void* src) {
    asm volatile("cp.async.cg.shared.global [%0], [%1], 16;" :: "r"(dst), "l"(src));
}
#define CP_COMMIT() asm volatile("cp.async.commit_group;" ::: "memory")
#define CP_WAIT1()  asm volatile("cp.async.wait_group 1;" ::: "memory")
#define CP_WAIT0()  asm volatile("cp.async.wait_group 0;" ::: "memory")

__device__ __forceinline__ void ldsm4(u32* r, u32 addr) {
    asm volatile("ldmatrix.sync.aligned.m8n8.x4.shared.b16 {%0,%1,%2,%3}, [%4];"
                 : "=r"(r[0]), "=r"(r[1]), "=r"(r[2]), "=r"(r[3]) : "r"(addr));
}
__device__ __forceinline__ void mma_bf16(float* d, const u32* a, const u32* b) {
    asm volatile("mma.sync.aligned.m16n8k16.row.col.f32.bf16.bf16.f32 "
                 "{%0,%1,%2,%3}, {%4,%5,%6,%7}, {%8,%9}, {%0,%1,%2,%3};"
                 : "+f"(d[0]), "+f"(d[1]), "+f"(d[2]), "+f"(d[3])
                 : "r"(a[0]), "r"(a[1]), "r"(a[2]), "r"(a[3]), "r"(b[0]), "r"(b[1]));
}
__device__ __forceinline__ void split_w(float v, __nv_bfloat16& h, __nv_bfloat16& l) {
    h = __float2bfloat16(v);
    l = __float2bfloat16(v - __bfloat162float(h));
}
// gate-paired row -> j (j = gate*1024 + cell):
// rows [0,64): cell pair {i,f}; rows [64,128): {g,o}
__device__ __forceinline__ int rowj(int nT, int n) {
    int half = n >> 6, m = n & 63;
    return (half * 2 + (m & 1)) * 1024 + nT * 32 + (m >> 1);
}

// ---------------- prep: biases (warp per j) ----------------
__global__ void prep_bias(const float* __restrict__ Wih, const float* __restrict__ bih,
                          const float* __restrict__ bhh, const float* __restrict__ bout)
{
    int w = threadIdx.x >> 5, lane = threadIdx.x & 31;
    int j = blockIdx.x * 8 + w;   // grid 512 x 256thr
    float acc = 0.f;
#pragma unroll
    for (int i = 0; i < 8; i++) acc += Wih[(size_t)j * 256 + i * 32 + lane] * bout[i * 32 + lane];
#pragma unroll
    for (int o = 16; o; o >>= 1) acc += __shfl_xor_sync(0xFFFFFFFFu, acc, o);
    if (lane == 0) {
        float s = bih[j] + bhh[j];
        g_b0[j] = s;
        g_bf[j] = s + acc;
    }
}

// ---------------- conv: Whh -> g_wbf[0] (coalesced reads) ----------------
__global__ void conv_w0(const float* __restrict__ Whh)
{
    int chunk = blockIdx.x, nT = blockIdx.y;
    int n = threadIdx.x;   // 128
    char* th = (char*)&g_wbf[0][nT][chunk][0][0];
    char* tl = th + 16384;
    const float* src = Whh + (size_t)rowj(nT, n) * 1024 + chunk * 64;
#pragma unroll 4
    for (int kk = 0; kk < 64; kk++) {
        __nv_bfloat16 h, l; split_w(src[kk], h, l);
        u32 off = swz((u32)(n * 128 + kk * 2));
        *(__nv_bfloat16*)(th + off) = h;
        *(__nv_bfloat16*)(tl + off) = l;
    }
}

// ---------------- conv: Wih -> g_pA (gate-paired rows, o cols) ----------------
__global__ void conv_wih(const float* __restrict__ Wih)
{
    int oc = blockIdx.x, nT = blockIdx.y;
    int n = threadIdx.x;   // 128
    char* th = (char*)&g_pA[nT][oc][0][0];
    char* tl = th + 16384;
    const float* src = Wih + (size_t)rowj(nT, n) * 256 + oc * 64;
#pragma unroll 4
    for (int kk = 0; kk < 64; kk++) {
        __nv_bfloat16 h, l; split_w(src[kk], h, l);
        u32 off = swz((u32)(n * 128 + kk * 2));
        *(__nv_bfloat16*)(th + off) = h;
        *(__nv_bfloat16*)(tl + off) = l;
    }
}

// ---------------- conv: Wout^T -> g_pB (rows k, cols o) ----------------
__global__ void conv_woutT(const float* __restrict__ Wout)
{
    int oc = blockIdx.x, kc = blockIdx.y;
    int k = threadIdx.x;   // 64
    char* th = (char*)&g_pB[kc][oc][0][0];
    char* tl = th + 8192;
#pragma unroll 4
    for (int oo = 0; oo < 64; oo++) {
        float v = Wout[(size_t)(oc * 64 + oo) * 1024 + kc * 64 + k];
        __nv_bfloat16 h, l; split_w(v, h, l);
        u32 off = swz((u32)(k * 128 + oo * 2));
        *(__nv_bfloat16*)(th + off) = h;
        *(__nv_bfloat16*)(tl + off) = l;
    }
}

// ---------------- conv: Wout -> g_obf (rows o, cols k) ----------------
__global__ void conv_obf(const float* __restrict__ Wout)
{
    int chunk = blockIdx.x, nOT = blockIdx.y;
    int n = threadIdx.x;   // 128
    char* th = (char*)&g_obf[nOT][chunk][0][0];
    char* tl = th + 16384;
    const float* src = Wout + (size_t)(nOT * 128 + n) * 1024 + chunk * 64;
#pragma unroll 4
    for (int kk = 0; kk < 64; kk++) {
        __nv_bfloat16 h, l; split_w(src[kk], h, l);
        u32 off = swz((u32)(n * 128 + kk * 2));
        *(__nv_bfloat16*)(th + off) = h;
        *(__nv_bfloat16*)(tl + off) = l;
    }
}

// ---------------- conv: encoder h0 -> g_hbf[0] ----------------
__global__ void conv_h0(const float* __restrict__ enc)
{
    int chunk = blockIdx.x, mT = blockIdx.y;
    char* th = (char*)&g_hbf[0][mT][chunk][0][0];
    char* tl = th + 16384;
#pragma unroll
    for (int i = 0; i < 32; i++) {
        int e = i * 256 + threadIdx.x;  // 0..8191
        int m = e >> 6, kk = e & 63;
        float v = enc[(size_t)(mT * 128 + m) * 1024 + chunk * 64 + kk];
        __nv_bfloat16 h, l; split_w(v, h, l);
        u32 off = swz((u32)(m * 128 + kk * 2));
        *(__nv_bfloat16*)(th + off) = h;
        *(__nv_bfloat16*)(tl + off) = l;
    }
}

// ---------------- prep GEMM: g_wbf[1] = split(Whh + Wih @ Wout^T), gate-paired ----------
// CTA (nT, kc): [128 j-rows] x [64 k-cols], contraction over o=256 (4 oc of 64).
#define PREP_SMEM (128*1024 + 64*1024 + 1024)
__global__ __launch_bounds__(256, 1) void prep_mma(const float* __restrict__ Whh)
{
    extern __shared__ char smem[];
    u32 sb = (smem_u32(smem) + 1023) & ~1023u;
    int tid = threadIdx.x, lane = tid & 31, w = tid >> 5;
    int nT = blockIdx.x, kc = blockIdx.y;

    const char* srcA = (const char*)&g_pA[nT][0][0][0];   // 128KB contiguous
    const char* srcB = (const char*)&g_pB[kc][0][0][0];   // 64KB contiguous
#pragma unroll
    for (int r = 0; r < 32; r++) { int idx = r * 256 + tid; cpa16(sb + idx * 16, srcA + (size_t)idx * 16); }
#pragma unroll
    for (int r = 0; r < 16; r++) { int idx = r * 256 + tid; cpa16(sb + 131072 + idx * 16, srcB + (size_t)idx * 16); }
    CP_COMMIT(); CP_WAIT0();
    __syncthreads();

    int wm = w >> 1, wn = w & 1;   // warps 4m x 2n: warp = 32 j-rows x 32 k-cols
    const int aRow = ((lane >> 3) & 1) * 8 + (lane & 7);
    const int aKh  = lane >> 4;
    const int bRow = (lane >> 4) * 8 + (lane & 7);
    const int bKh  = (lane >> 3) & 1;

    float d[2][4][4] = {};
#pragma unroll
    for (int oc = 0; oc < 4; oc++) {
        u32 stA = sb + oc * 32768;
        u32 stB = sb + 131072 + oc * 16384;
#pragma unroll
        for (int k16 = 0; k16 < 4; k16++) {
            u32 aH[2][4], aL[2][4];
#pragma unroll
            for (int mi = 0; mi < 2; mi++) {
                u32 off = swz((u32)((wm * 32 + mi * 16 + aRow) * 128 + (k16 * 2 + aKh) * 16));
                ldsm4(aH[mi], stA + off);
                ldsm4(aL[mi], stA + 16384 + off);
            }
            u32 bH[2][4], bL[2][4];
#pragma unroll
            for (int bi = 0; bi < 2; bi++) {
                u32 off = swz((u32)((wn * 32 + bi * 16 + bRow) * 128 + (k16 * 2 + bKh) * 16));
                ldsm4(bH[bi], stB + off);
                ldsm4(bL[bi], stB + 8192 + off);
            }
#pragma unroll
            for (int mi = 0; mi < 2; mi++)
#pragma unroll
                for (int nj = 0; nj < 4; nj++) {
                    mma_bf16(d[mi][nj], aH[mi], &bH[nj >> 1][(nj & 1) * 2]);
                    mma_bf16(d[mi][nj], aH[mi], &bL[nj >> 1][(nj & 1) * 2]);
                    mma_bf16(d[mi][nj], aL[mi], &bH[nj >> 1][(nj & 1) * 2]);
                }
        }
    }

    // epilogue: add Whh, split, write g_wbf[1]
    char* th = (char*)&g_wbf[1][nT][kc][0][0];
    char* tl = th + 16384;
#pragma unroll
    for (int mi = 0; mi < 2; mi++)
#pragma unroll
        for (int nj = 0; nj < 4; nj++)
#pragma unroll
            for (int rh = 0; rh < 2; rh++) {
                int n = wm * 32 + mi * 16 + (lane >> 2) + rh * 8;
                int j = rowj(nT, n);
                int k0l = wn * 32 + nj * 8 + 2 * (lane & 3);
                const float* wr = Whh + (size_t)j * 1024 + kc * 64 + k0l;
                float v0 = d[mi][nj][rh * 2 + 0] + wr[0];
                float v1 = d[mi][nj][rh * 2 + 1] + wr[1];
                __nv_bfloat16 h0, l0, h1, l1;
                split_w(v0, h0, l0); split_w(v1, h1, l1);
                u32 off = swz((u32)(n * 128 + k0l * 2));
                *(u32*)(th + off) = (u32)__bfloat16_as_ushort(h0) | ((u32)__bfloat16_as_ushort(h1) << 16);
                *(u32*)(tl + off) = (u32)__bfloat16_as_ushort(l0) | ((u32)__bfloat16_as_ushort(l1) << 16);
            }
}

// ---------------- LSTM step: CTA 128 batch x 128 gate-cols, K=1024 (16 chunks) --------
#define LSTAGE 65536
#define LSTM_SMEM (2*LSTAGE + 1024)
__global__ __launch_bounds__(256, 1) void lstm_mma(int t)
{
    extern __shared__ char smem[];
    u32 sb = (smem_u32(smem) + 1023) & ~1023u;
    int tid = threadIdx.x, lane = tid & 31, w = tid >> 5;
    int mT = blockIdx.x, nT = blockIdx.y;
    const int ws = (t == 1) ? 0 : 1;
    const int first = (t == 1);

    const char* srcA = (const char*)&g_hbf[t - 1][mT][0][0][0];  // chunk stride 32KB
    const char* srcB = (const char*)&g_wbf[ws][nT][0][0][0];     // chunk stride 32KB

#pragma unroll
    for (int pc = 0; pc < 2; pc++) {
        u32 stg = sb + pc * LSTAGE;
        const char* a = srcA + (size_t)pc * 32768;
        const char* b = srcB + (size_t)pc * 32768;
#pragma unroll
        for (int r = 0; r < 8; r++) { int idx = r * 256 + tid; cpa16(stg + idx * 16, a + (size_t)idx * 16); }
#pragma unroll
        for (int r = 0; r < 8; r++) { int idx = r * 256 + tid; cpa16(stg + 32768 + idx * 16, b + (size_t)idx * 16); }
        CP_COMMIT();
    }

    int wm = w >> 2, wn = w & 3;   // warps 2m x 4n: warp = 64 batch x (16 IF + 16 GO rows)
    const int aRow = ((lane >> 3) & 1) * 8 + (lane & 7);
    const int aKh  = lane >> 4;
    const int bRow = (lane >> 4) * 8 + (lane & 7);
    const int bKh  = (lane >> 3) & 1;

    float d[4][4][4] = {};   // [mi][nj: 0,1=IF 2,3=GO][frag]

    for (int c = 0; c < 16; c++) {
        int s = c & 1;
        CP_WAIT1();
        __syncthreads();
        u32 stA = sb + s * LSTAGE;
        u32 stB = stA + 32768;
#pragma unroll
        for (int k16 = 0; k16 < 4; k16++) {
            u32 aH[4][4], aL[4][4];
#pragma unroll
            for (int mi = 0; mi < 4; mi++) {
                u32 off = swz((u32)((wm * 64 + mi * 16 + aRow) * 128 + (k16 * 2 + aKh) * 16));
                ldsm4(aH[mi], stA + off);
                ldsm4(aL[mi], stA + 16384 + off);
            }
            u32 bIFh[4], bIFl[4], bGOh[4], bGOl[4];
            {
                u32 offIF = swz((u32)((wn * 16 + bRow) * 128 + (k16 * 2 + bKh) * 16));
                u32 offGO = swz((u32)((64 + wn * 16 + bRow) * 128 + (k16 * 2 + bKh) * 16));
                ldsm4(bIFh, stB + offIF); ldsm4(bIFl, stB + 16384 + offIF);
                ldsm4(bGOh, stB + offGO); ldsm4(bGOl, stB + 16384 + offGO);
            }
#pragma unroll
            for (int mi = 0; mi < 4; mi++)
#pragma unroll
                for (int nj = 0; nj < 2; nj++) {
                    mma_bf16(d[mi][nj],     aH[mi], &bIFh[nj * 2]);
                    mma_bf16(d[mi][nj],     aH[mi], &bIFl[nj * 2]);
                    mma_bf16(d[mi][nj],     aL[mi], &bIFh[nj * 2]);
                    mma_bf16(d[mi][nj + 2], aH[mi], &bGOh[nj * 2]);
                    mma_bf16(d[mi][nj + 2], aH[mi], &bGOl[nj * 2]);
                    mma_bf16(d[mi][nj + 2], aL[mi], &bGOh[nj * 2]);
                }
        }
        __syncthreads();
        if (c + 2 < 16) {
            u32 stg = sb + s * LSTAGE;
            const char* a = srcA + (size_t)(c + 2) * 32768;
            const char* b = srcB + (size_t)(c + 2) * 32768;
#pragma unroll
            for (int r = 0; r < 8; r++) { int idx = r * 256 + tid; cpa16(stg + idx * 16, a + (size_t)idx * 16); }
#pragma unroll
            for (int r = 0; r < 8; r++) { int idx = r * 256 + tid; cpa16(stg + 32768 + idx * 16, b + (size_t)idx * 16); }
        }
        CP_COMMIT();
    }

    // ---- epilogue: LSTM cell update + emit next A tile (bf16 hi/lo) ----
    const float* bias = first ? g_b0 : g_bf;
    const float* c_in = g_c + (size_t)((t - 1) & 1) * HB;
    float* c_out = g_c + (size_t)(t & 1) * HB;
    const int chunk = nT >> 1;
    char* dh = (char*)&g_hbf[t][mT][chunk][0][0];
    char* dl = dh + 16384;

#pragma unroll
    for (int mi = 0; mi < 4; mi++)
#pragma unroll
        for (int rh = 0; rh < 2; rh++) {
            int bl = wm * 64 + mi * 16 + (lane >> 2) + rh * 8;   // 0..127
            int b = mT * 128 + bl;
#pragma unroll
            for (int cp = 0; cp < 2; cp++) {
                int cl = wn * 8 + cp * 4 + (lane & 3);           // 0..31
                int cell = nT * 32 + cl;
                float gi = d[mi][cp][rh * 2 + 0] + bias[cell];
                float gf = d[mi][cp][rh * 2 + 1] + bias[1024 + cell];
                float gg = d[mi][cp + 2][rh * 2 + 0] + bias[2048 + cell];
                float go = d[mi][cp + 2][rh * 2 + 1] + bias[3072 + cell];
                float cold = first ? 0.f : c_in[(size_t)cell * 512 + b];
                float cn = sigm(gf) * cold + sigm(gi) * tanhf(gg);
                float hn = sigm(go) * tanhf(cn);
                c_out[(size_t)cell * 512 + b] = cn;
                __nv_bfloat16 hh, hl; split_w(hn, hh, hl);
                int kin = (nT & 1) * 32 + cl;
                u32 off = swz((u32)(bl * 128 + kin * 2));
                *(__nv_bfloat16*)(dh + off) = hh;
                *(__nv_bfloat16*)(dl + off) = hl;
            }
        }
}

// ---------------- output GEMM: out[b][t][o] = h_t @ Wout^T + b_out (mma, 3-pass) ------
__global__ __launch_bounds__(256, 1) void out_mma(const float* __restrict__ bout,
                                                  float* __restrict__ out)
{
    extern __shared__ char smem[];
    u32 sb = (smem_u32(smem) + 1023) & ~1023u;
    int tid = threadIdx.x, lane = tid & 31, w = tid >> 5;
    int mT = blockIdx.x, nOT = blockIdx.y, t = blockIdx.z;

    const char* srcA = (const char*)&g_hbf[t + 1][mT][0][0][0];
    const char* srcB = (const char*)&g_obf[nOT][0][0][0];

#pragma unroll
    for (int pc = 0; pc < 2; pc++) {
        u32 stg = sb + pc * LSTAGE;
        const char* a = srcA + (size_t)pc * 32768;
        const char* b = srcB + (size_t)pc * 32768;
#pragma unroll
        for (int r = 0; r < 8; r++) { int idx = r * 256 + tid; cpa16(stg + idx * 16, a + (size_t)idx * 16); }
#pragma unroll
        for (int r = 0; r < 8; r++) { int idx = r * 256 + tid; cpa16(stg + 32768 + idx * 16, b + (size_t)idx * 16); }
        CP_COMMIT();
    }

    int wm = w >> 2, wn = w & 3;   // 2m x 4n: warp = 64 batch x 32 o
    const int aRow = ((lane >> 3) & 1) * 8 + (lane & 7);
    const int aKh  = lane >> 4;
    const int bRow = (lane >> 4) * 8 + (lane & 7);
    const int bKh  = (lane >> 3) & 1;

    float d[4][4][4] = {};

    for (int c = 0; c < 16; c++) {
        int s = c & 1;
        CP_WAIT1();
        __syncthreads();
        u32 stA = sb + s * LSTAGE;
        u32 stB = stA + 32768;
#pragma unroll
        for (int k16 = 0; k16 < 4; k16++) {
            u32 aH[4][4], aL[4][4];
#pragma unroll
            for (int mi = 0; mi < 4; mi++) {
                u32 off = swz((u32)((wm * 64 + mi * 16 + aRow) * 128 + (k16 * 2 + aKh) * 16));
                ldsm4(aH[mi], stA + off);
                ldsm4(aL[mi], stA + 16384 + off);
            }
            u32 bH[2][4], bL[2][4];
#pragma unroll
            for (int bi = 0; bi < 2; bi++) {
                u32 off = swz((u32)((wn * 32 + bi * 16 + bRow) * 128 + (k16 * 2 + bKh) * 16));
                ldsm4(bH[bi], stB + off);
                ldsm4(bL[bi], stB + 16384 + off);
            }
#pragma unroll
            for (int mi = 0; mi < 4; mi++)
#pragma unroll
                for (int nj = 0; nj < 4; nj++) {
                    mma_bf16(d[mi][nj], aH[mi], &bH[nj >> 1][(nj & 1) * 2]);
                    mma_bf16(d[mi][nj], aH[mi], &bL[nj >> 1][(nj & 1) * 2]);
                    mma_bf16(d[mi][nj], aL[mi], &bH[nj >> 1][(nj & 1) * 2]);
                }
        }
        __syncthreads();
        if (c + 2 < 16) {
            u32 stg = sb + s * LSTAGE;
            const char* a = srcA + (size_t)(c + 2) * 32768;
            const char* b = srcB + (size_t)(c + 2) * 32768;
#pragma unroll
            for (int r = 0; r < 8; r++) { int idx = r * 256 + tid; cpa16(stg + idx * 16, a + (size_t)idx * 16); }
#pragma unroll
            for (int r = 0; r < 8; r++) { int idx = r * 256 + tid; cpa16(stg + 32768 + idx * 16, b + (size_t)idx * 16); }
        }
        CP_COMMIT();
    }

#pragma unroll
    for (int mi = 0; mi < 4; mi++)
#pragma unroll
        for (int nj = 0; nj < 4; nj++)
#pragma unroll
            for (int rh = 0; rh < 2; rh++) {
                int bl = wm * 64 + mi * 16 + (lane >> 2) + rh * 8;
                int b = mT * 128 + bl;
                int o = nOT * 128 + wn * 32 + nj * 8 + 2 * (lane & 3);
                float2 v = make_float2(d[mi][nj][rh * 2 + 0] + bout[o],
                                       d[mi][nj][rh * 2 + 1] + bout[o + 1]);
                *(float2*)&out[(size_t)b * 32768 + (size_t)t * 256 + o] = v;
            }
}

// ---------------- launch ----------------
extern "C" void kernel_launch(void* const* d_in, const int* in_sizes, int n_in,
                              void* d_out, int out_size)
{
    const float *enc = nullptr, *Wih = nullptr, *Whh = nullptr;
    const float *bih = nullptr, *bhh = nullptr, *Wout = nullptr, *bout = nullptr;
    for (int i = 0; i < n_in; i++) {
        int s = in_sizes[i];
        if      (s == 512 * 1024)  enc  = (const float*)d_in[i];
        else if (s == 4096 * 256)  Wih  = (const float*)d_in[i];
        else if (s == 4096 * 1024) Whh  = (const float*)d_in[i];
        else if (s == 4096)        { if (!bih) bih = (const float*)d_in[i]; else bhh = (const float*)d_in[i]; }
        else if (s == 256 * 1024)  Wout = (const float*)d_in[i];
        else if (s == 256)         bout = (const float*)d_in[i];
    }
    if (!enc || !Wih || !Whh || !bih || !bhh || !Wout || !bout) return;

    cudaFuncSetAttribute(prep_mma, cudaFuncAttributeMaxDynamicSharedMemorySize, PREP_SMEM);
    cudaFuncSetAttribute(lstm_mma, cudaFuncAttributeMaxDynamicSharedMemorySize, LSTM_SMEM);
    cudaFuncSetAttribute(out_mma,  cudaFuncAttributeMaxDynamicSharedMemorySize, LSTM_SMEM);

    prep_bias<<<512, 256>>>(Wih, bih, bhh, bout);
    conv_w0<<<dim3(16, 32), 128>>>(Whh);
    conv_wih<<<dim3(4, 32), 128>>>(Wih);
    conv_woutT<<<dim3(4, 16), 64>>>(Wout);
    conv_obf<<<dim3(16, 2), 128>>>(Wout);
    conv_h0<<<dim3(16, 4), 256>>>(enc);
    prep_mma<<<dim3(32, 16), 256, PREP_SMEM>>>(Whh);

    for (int t = 1; t <= 128; t++)
        lstm_mma<<<dim3(4, 32), 256, LSTM_SMEM>>>(t);

    out_mma<<<dim3(4, 2, 128), 256, LSTM_SMEM>>>(bout, (float*)d_out);
    (void)out_size;
}

// round 6
// speedup vs baseline: 3.0238x; 1.0205x over previous
#include <cuda_runtime.h>
#include <cuda_bf16.h>
#include <cstdint>

typedef unsigned long long ull;
typedef unsigned int u32;

#define HB (1024*512)

// ---------------- scratch (static __device__, no allocations) ----------------
static __device__ float g_b0[4096];               // b_ih+b_hh
static __device__ float g_bf[4096];               // + W_ih@b_out
static __device__ u32   g_bar[516];               // per-(t,mT) arrival counters
// weight tiles, gate-paired rows, SW128 pre-swizzled: [src][nT 32][chunk 16][part 2][128x64]
static __device__ __align__(256) __nv_bfloat16 g_wbf[2][32][16][2][8192];
// hidden tiles: [t 0..128][mT 4][chunk 16][part 2][128x64]
static __device__ __align__(256) __nv_bfloat16 g_hbf[129][4][16][2][8192];
// output-weight tiles: [nOT 2][chunk 16][part 2][128x64]
static __device__ __align__(256) __nv_bfloat16 g_obf[2][16][2][8192];
// prep-GEMM operands: Wih gate-paired [nT][oc 4][part][128x64]; WoutT [kc 16][oc 4][part][64x64]
static __device__ __align__(256) __nv_bfloat16 g_pA[32][4][2][8192];
static __device__ __align__(256) __nv_bfloat16 g_pB[16][4][2][4096];

// ---------------- helpers ----------------
__device__ __forceinline__ float sigm(float x) { return 1.0f / (1.0f + __expf(-x)); }
__device__ __forceinline__ u32 swz(u32 x) { return x ^ ((x >> 3) & 0x70); }
__device__ __forceinline__ u32 smem_u32(const void* p) {
    u32 a; asm("{ .reg .u64 t; cvta.to.shared.u64 t, %1; cvt.u32.u64 %0, t; }" : "=r"(a) : "l"(p));
    return a;
}
__device__ __forceinline__ void cpa16(u32 dst, const void* src) {
    asm volatile("cp.async.cg.shared.global [%0], [%1], 16;" :: "r"(dst), "l"(src));
}
#define CP_COMMIT() asm volatile("cp.async.commit_group;" ::: "memory")
#define CP_WAIT1()  asm volatile("cp.async.wait_group 1;" ::: "memory")
#define CP_WAIT0()  asm volatile("cp.async.wait_group 0;" ::: "memory")

__device__ __forceinline__ void ldsm4(u32* r, u32 addr) {
    asm volatile("ldmatrix.sync.aligned.m8n8.x4.shared.b16 {%0,%1,%2,%3}, [%4];"
                 : "=r"(r[0]), "=r"(r[1]), "=r"(r[2]), "=r"(r[3]) : "r"(addr));
}
__device__ __forceinline__ void mma_bf16(float* d, const u32* a, const u32* b) {
    asm volatile("mma.sync.aligned.m16n8k16.row.col.f32.bf16.bf16.f32 "
                 "{%0,%1,%2,%3}, {%4,%5,%6,%7}, {%8,%9}, {%0,%1,%2,%3};"
                 : "+f"(d[0]), "+f"(d[1]), "+f"(d[2]), "+f"(d[3])
                 : "r"(a[0]), "r"(a[1]), "r"(a[2]), "r"(a[3]), "r"(b[0]), "r"(b[1]));
}
__device__ __forceinline__ void split_w(float v, __nv_bfloat16& h, __nv_bfloat16& l) {
    h = __float2bfloat16(v);
    l = __float2bfloat16(v - __bfloat162float(h));
}
// gate-paired row -> j (j = gate*1024 + cell):
// rows [0,64): cell pair {i,f}; rows [64,128): {g,o}
__device__ __forceinline__ int rowj(int nT, int n) {
    int half = n >> 6, m = n & 63;
    return (half * 2 + (m & 1)) * 1024 + nT * 32 + (m >> 1);
}

// ---------------- init barrier counters ----------------
__global__ void init_bar() {
    int i = blockIdx.x * 256 + threadIdx.x;
    if (i < 516) g_bar[i] = 0;
}

// ---------------- prep: biases (warp per j) ----------------
__global__ void prep_bias(const float* __restrict__ Wih, const float* __restrict__ bih,
                          const float* __restrict__ bhh, const float* __restrict__ bout)
{
    int w = threadIdx.x >> 5, lane = threadIdx.x & 31;
    int j = blockIdx.x * 8 + w;
    float acc = 0.f;
#pragma unroll
    for (int i = 0; i < 8; i++) acc += Wih[(size_t)j * 256 + i * 32 + lane] * bout[i * 32 + lane];
#pragma unroll
    for (int o = 16; o; o >>= 1) acc += __shfl_xor_sync(0xFFFFFFFFu, acc, o);
    if (lane == 0) {
        float s = bih[j] + bhh[j];
        g_b0[j] = s;
        g_bf[j] = s + acc;
    }
}

// ---------------- conv: Whh -> g_wbf[0] ----------------
__global__ void conv_w0(const float* __restrict__ Whh)
{
    int chunk = blockIdx.x, nT = blockIdx.y;
    int n = threadIdx.x;
    char* th = (char*)&g_wbf[0][nT][chunk][0][0];
    char* tl = th + 16384;
    const float* src = Whh + (size_t)rowj(nT, n) * 1024 + chunk * 64;
#pragma unroll 4
    for (int kk = 0; kk < 64; kk++) {
        __nv_bfloat16 h, l; split_w(src[kk], h, l);
        u32 off = swz((u32)(n * 128 + kk * 2));
        *(__nv_bfloat16*)(th + off) = h;
        *(__nv_bfloat16*)(tl + off) = l;
    }
}

// ---------------- conv: Wih -> g_pA ----------------
__global__ void conv_wih(const float* __restrict__ Wih)
{
    int oc = blockIdx.x, nT = blockIdx.y;
    int n = threadIdx.x;
    char* th = (char*)&g_pA[nT][oc][0][0];
    char* tl = th + 16384;
    const float* src = Wih + (size_t)rowj(nT, n) * 256 + oc * 64;
#pragma unroll 4
    for (int kk = 0; kk < 64; kk++) {
        __nv_bfloat16 h, l; split_w(src[kk], h, l);
        u32 off = swz((u32)(n * 128 + kk * 2));
        *(__nv_bfloat16*)(th + off) = h;
        *(__nv_bfloat16*)(tl + off) = l;
    }
}

// ---------------- conv: Wout^T -> g_pB (256 threads) ----------------
__global__ void conv_woutT(const float* __restrict__ Wout)
{
    int oc = blockIdx.x, kc = blockIdx.y;
    int k = threadIdx.x & 63, og = threadIdx.x >> 6;
    char* th = (char*)&g_pB[kc][oc][0][0];
    char* tl = th + 8192;
#pragma unroll
    for (int i = 0; i < 16; i++) {
        int oo = og * 16 + i;
        float v = Wout[(size_t)(oc * 64 + oo) * 1024 + kc * 64 + k];
        __nv_bfloat16 h, l; split_w(v, h, l);
        u32 off = swz((u32)(k * 128 + oo * 2));
        *(__nv_bfloat16*)(th + off) = h;
        *(__nv_bfloat16*)(tl + off) = l;
    }
}

// ---------------- conv: Wout -> g_obf ----------------
__global__ void conv_obf(const float* __restrict__ Wout)
{
    int chunk = blockIdx.x, nOT = blockIdx.y;
    int n = threadIdx.x;
    char* th = (char*)&g_obf[nOT][chunk][0][0];
    char* tl = th + 16384;
    const float* src = Wout + (size_t)(nOT * 128 + n) * 1024 + chunk * 64;
#pragma unroll 4
    for (int kk = 0; kk < 64; kk++) {
        __nv_bfloat16 h, l; split_w(src[kk], h, l);
        u32 off = swz((u32)(n * 128 + kk * 2));
        *(__nv_bfloat16*)(th + off) = h;
        *(__nv_bfloat16*)(tl + off) = l;
    }
}

// ---------------- conv: encoder h0 -> g_hbf[0] ----------------
__global__ void conv_h0(const float* __restrict__ enc)
{
    int chunk = blockIdx.x, mT = blockIdx.y;
    char* th = (char*)&g_hbf[0][mT][chunk][0][0];
    char* tl = th + 16384;
#pragma unroll
    for (int i = 0; i < 32; i++) {
        int e = i * 256 + threadIdx.x;
        int m = e >> 6, kk = e & 63;
        float v = enc[(size_t)(mT * 128 + m) * 1024 + chunk * 64 + kk];
        __nv_bfloat16 h, l; split_w(v, h, l);
        u32 off = swz((u32)(m * 128 + kk * 2));
        *(__nv_bfloat16*)(th + off) = h;
        *(__nv_bfloat16*)(tl + off) = l;
    }
}

// ---------------- prep GEMM: g_wbf[1] = split(Whh + Wih @ Wout^T) ----------
#define PREP_SMEM (128*1024 + 64*1024 + 1024)
__global__ __launch_bounds__(256, 1) void prep_mma(const float* __restrict__ Whh)
{
    extern __shared__ char smem[];
    u32 sb = (smem_u32(smem) + 1023) & ~1023u;
    int tid = threadIdx.x, lane = tid & 31, w = tid >> 5;
    int nT = blockIdx.x, kc = blockIdx.y;

    const char* srcA = (const char*)&g_pA[nT][0][0][0];
    const char* srcB = (const char*)&g_pB[kc][0][0][0];
#pragma unroll
    for (int r = 0; r < 32; r++) { int idx = r * 256 + tid; cpa16(sb + idx * 16, srcA + (size_t)idx * 16); }
#pragma unroll
    for (int r = 0; r < 16; r++) { int idx = r * 256 + tid; cpa16(sb + 131072 + idx * 16, srcB + (size_t)idx * 16); }
    CP_COMMIT(); CP_WAIT0();
    __syncthreads();

    int wm = w >> 1, wn = w & 1;
    const int aRow = ((lane >> 3) & 1) * 8 + (lane & 7);
    const int aKh  = lane >> 4;
    const int bRow = (lane >> 4) * 8 + (lane & 7);
    const int bKh  = (lane >> 3) & 1;

    float d[2][4][4] = {};
#pragma unroll
    for (int oc = 0; oc < 4; oc++) {
        u32 stA = sb + oc * 32768;
        u32 stB = sb + 131072 + oc * 16384;
#pragma unroll
        for (int k16 = 0; k16 < 4; k16++) {
            u32 aH[2][4], aL[2][4];
#pragma unroll
            for (int mi = 0; mi < 2; mi++) {
                u32 off = swz((u32)((wm * 32 + mi * 16 + aRow) * 128 + (k16 * 2 + aKh) * 16));
                ldsm4(aH[mi], stA + off);
                ldsm4(aL[mi], stA + 16384 + off);
            }
            u32 bH[2][4], bL[2][4];
#pragma unroll
            for (int bi = 0; bi < 2; bi++) {
                u32 off = swz((u32)((wn * 32 + bi * 16 + bRow) * 128 + (k16 * 2 + bKh) * 16));
                ldsm4(bH[bi], stB + off);
                ldsm4(bL[bi], stB + 8192 + off);
            }
#pragma unroll
            for (int mi = 0; mi < 2; mi++)
#pragma unroll
                for (int nj = 0; nj < 4; nj++) {
                    mma_bf16(d[mi][nj], aH[mi], &bH[nj >> 1][(nj & 1) * 2]);
                    mma_bf16(d[mi][nj], aH[mi], &bL[nj >> 1][(nj & 1) * 2]);
                    mma_bf16(d[mi][nj], aL[mi], &bH[nj >> 1][(nj & 1) * 2]);
                }
        }
    }

    char* th = (char*)&g_wbf[1][nT][kc][0][0];
    char* tl = th + 16384;
#pragma unroll
    for (int mi = 0; mi < 2; mi++)
#pragma unroll
        for (int nj = 0; nj < 4; nj++)
#pragma unroll
            for (int rh = 0; rh < 2; rh++) {
                int n = wm * 32 + mi * 16 + (lane >> 2) + rh * 8;
                int j = rowj(nT, n);
                int k0l = wn * 32 + nj * 8 + 2 * (lane & 3);
                const float* wr = Whh + (size_t)j * 1024 + kc * 64 + k0l;
                float v0 = d[mi][nj][rh * 2 + 0] + wr[0];
                float v1 = d[mi][nj][rh * 2 + 1] + wr[1];
                __nv_bfloat16 h0, l0, h1, l1;
                split_w(v0, h0, l0); split_w(v1, h1, l1);
                u32 off = swz((u32)(n * 128 + k0l * 2));
                *(u32*)(th + off) = (u32)__bfloat16_as_ushort(h0) | ((u32)__bfloat16_as_ushort(h1) << 16);
                *(u32*)(tl + off) = (u32)__bfloat16_as_ushort(l0) | ((u32)__bfloat16_as_ushort(l1) << 16);
            }
}

// ---------------- persistent LSTM: all 128 steps in one kernel ----------------
// grid (4 mT, 32 nT) = 128 CTAs, all resident. Per-group (mT) release/acquire barrier.
// c state in registers. B chunks 0/1 of next step prefetched during drain.
#define LSTAGE 65536
#define LSTM_SMEM (2*LSTAGE + 1024)
__global__ __launch_bounds__(256, 1) void lstm_persist()
{
    extern __shared__ char smem[];
    u32 sb = (smem_u32(smem) + 1023) & ~1023u;
    const int tid = threadIdx.x, lane = tid & 31, w = tid >> 5;
    const int mT = blockIdx.x, nT = blockIdx.y;
    const int wm = w >> 2, wn = w & 3;
    const int aRow = ((lane >> 3) & 1) * 8 + (lane & 7);
    const int aKh  = lane >> 4;
    const int bRow = (lane >> 4) * 8 + (lane & 7);
    const int bKh  = (lane >> 3) & 1;

    auto fillA = [&](int c, int s, const char* src) {
#pragma unroll
        for (int r = 0; r < 8; r++) {
            int idx = r * 256 + tid;
            cpa16(sb + s * LSTAGE + idx * 16, src + (size_t)c * 32768 + idx * 16);
        }
    };
    auto fillB = [&](int c, int s, const char* src) {
#pragma unroll
        for (int r = 0; r < 8; r++) {
            int idx = r * 256 + tid;
            cpa16(sb + s * LSTAGE + 32768 + idx * 16, src + (size_t)c * 32768 + idx * 16);
        }
    };

    // bias registers (cell depends only on cp)
    float bZ[2][4], bF[2][4];
#pragma unroll
    for (int cp = 0; cp < 2; cp++) {
        int cell = nT * 32 + wn * 8 + cp * 4 + (lane & 3);
#pragma unroll
        for (int g = 0; g < 4; g++) {
            bZ[cp][g] = g_b0[g * 1024 + cell];
            bF[cp][g] = g_bf[g * 1024 + cell];
        }
    }

    float creg[4][2][2];   // cell state in registers
#pragma unroll
    for (int mi = 0; mi < 4; mi++)
#pragma unroll
        for (int rh = 0; rh < 2; rh++)
#pragma unroll
            for (int cp = 0; cp < 2; cp++) creg[mi][rh][cp] = 0.f;

    const char* srcBn = (const char*)&g_wbf[1][nT][0][0][0];   // steady-state weights

    // prologue: B0,B1,A0,A1 as 4 groups (order matters for wait_group 1)
    {
        const char* B1 = (const char*)&g_wbf[0][nT][0][0][0];
        const char* A1 = (const char*)&g_hbf[0][mT][0][0][0];
        fillB(0, 0, B1); CP_COMMIT();
        fillB(1, 1, B1); CP_COMMIT();
        fillA(0, 0, A1); CP_COMMIT();
        fillA(1, 1, A1); CP_COMMIT();
    }

    for (int t = 1; t <= 128; t++) {
        const int first = (t == 1);
        const char* srcA = (const char*)&g_hbf[t - 1][mT][0][0][0];
        const char* srcB = first ? (const char*)&g_wbf[0][nT][0][0][0] : srcBn;

        float d[4][4][4];
#pragma unroll
        for (int mi = 0; mi < 4; mi++)
#pragma unroll
            for (int nj = 0; nj < 4; nj++)
#pragma unroll
                for (int q = 0; q < 4; q++) d[mi][nj][q] = 0.f;

        for (int c = 0; c < 16; c++) {
            int s = c & 1;
            CP_WAIT1();
            __syncthreads();
            u32 stA = sb + s * LSTAGE;
            u32 stB = stA + 32768;
#pragma unroll
            for (int k16 = 0; k16 < 4; k16++) {
                u32 aH[4][4], aL[4][4];
#pragma unroll
                for (int mi = 0; mi < 4; mi++) {
                    u32 off = swz((u32)((wm * 64 + mi * 16 + aRow) * 128 + (k16 * 2 + aKh) * 16));
                    ldsm4(aH[mi], stA + off);
                    ldsm4(aL[mi], stA + 16384 + off);
                }
                u32 bIFh[4], bIFl[4], bGOh[4], bGOl[4];
                {
                    u32 offIF = swz((u32)((wn * 16 + bRow) * 128 + (k16 * 2 + bKh) * 16));
                    u32 offGO = swz((u32)((64 + wn * 16 + bRow) * 128 + (k16 * 2 + bKh) * 16));
                    ldsm4(bIFh, stB + offIF); ldsm4(bIFl, stB + 16384 + offIF);
                    ldsm4(bGOh, stB + offGO); ldsm4(bGOl, stB + 16384 + offGO);
                }
#pragma unroll
                for (int mi = 0; mi < 4; mi++)
#pragma unroll
                    for (int nj = 0; nj < 2; nj++) {
                        mma_bf16(d[mi][nj],     aH[mi], &bIFh[nj * 2]);
                        mma_bf16(d[mi][nj],     aH[mi], &bIFl[nj * 2]);
                        mma_bf16(d[mi][nj],     aL[mi], &bIFh[nj * 2]);
                        mma_bf16(d[mi][nj + 2], aH[mi], &bGOh[nj * 2]);
                        mma_bf16(d[mi][nj + 2], aH[mi], &bGOl[nj * 2]);
                        mma_bf16(d[mi][nj + 2], aL[mi], &bGOh[nj * 2]);
                    }
            }
            __syncthreads();
            if (c + 2 < 16) {
                fillA(c + 2, s, srcA);
                fillB(c + 2, s, srcB);
            } else if (t < 128) {
                fillB(c - 14, s, srcBn);     // next step's B chunk 0/1 (h-independent)
            }
            CP_COMMIT();
        }

        // ---- epilogue: LSTM cell update (c in regs) + emit next A tile ----
        {
            const int chunk = nT >> 1;
            char* dh = (char*)&g_hbf[t][mT][chunk][0][0];
            char* dl = dh + 16384;
#pragma unroll
            for (int mi = 0; mi < 4; mi++)
#pragma unroll
                for (int rh = 0; rh < 2; rh++) {
                    int bl = wm * 64 + mi * 16 + (lane >> 2) + rh * 8;
#pragma unroll
                    for (int cp = 0; cp < 2; cp++) {
                        int cl = wn * 8 + cp * 4 + (lane & 3);
                        float gi = d[mi][cp][rh * 2 + 0]     + (first ? bZ[cp][0] : bF[cp][0]);
                        float gf = d[mi][cp][rh * 2 + 1]     + (first ? bZ[cp][1] : bF[cp][1]);
                        float gg = d[mi][cp + 2][rh * 2 + 0] + (first ? bZ[cp][2] : bF[cp][2]);
                        float go = d[mi][cp + 2][rh * 2 + 1] + (first ? bZ[cp][3] : bF[cp][3]);
                        float cold = first ? 0.f : creg[mi][rh][cp];
                        float cn = sigm(gf) * cold + sigm(gi) * tanhf(gg);
                        float hn = sigm(go) * tanhf(cn);
                        creg[mi][rh][cp] = cn;
                        __nv_bfloat16 hh, hl; split_w(hn, hh, hl);
                        int kin = (nT & 1) * 32 + cl;
                        u32 off = swz((u32)(bl * 128 + kin * 2));
                        *(__nv_bfloat16*)(dh + off) = hh;
                        *(__nv_bfloat16*)(dl + off) = hl;
                    }
                }
        }

        if (t < 128) {
            __syncthreads();                 // all epilogue STGs issued
            if (tid == 0) {
                __threadfence();
                u32* bp = &g_bar[t * 4 + mT];
                asm volatile("red.release.gpu.global.add.u32 [%0], %1;" :: "l"(bp), "r"(1u) : "memory");
                u32 v;
                do {
                    asm volatile("ld.acquire.gpu.global.u32 %0, [%1];" : "=r"(v) : "l"(bp) : "memory");
                } while (v < 32);
            }
            __syncthreads();
            const char* An = (const char*)&g_hbf[t][mT][0][0][0];
            fillA(0, 0, An); CP_COMMIT();
            fillA(1, 1, An); CP_COMMIT();
        }
    }
}

// ---------------- output GEMM: out[b][t][o] = h_{t+1} @ Wout^T + b_out ------
__global__ __launch_bounds__(256, 1) void out_mma(const float* __restrict__ bout,
                                                  float* __restrict__ out)
{
    extern __shared__ char smem[];
    u32 sb = (smem_u32(smem) + 1023) & ~1023u;
    int tid = threadIdx.x, lane = tid & 31, w = tid >> 5;
    int mT = blockIdx.x, nOT = blockIdx.y, t = blockIdx.z;

    const char* srcA = (const char*)&g_hbf[t + 1][mT][0][0][0];
    const char* srcB = (const char*)&g_obf[nOT][0][0][0];

#pragma unroll
    for (int pc = 0; pc < 2; pc++) {
        u32 stg = sb + pc * LSTAGE;
        const char* a = srcA + (size_t)pc * 32768;
        const char* b = srcB + (size_t)pc * 32768;
#pragma unroll
        for (int r = 0; r < 8; r++) { int idx = r * 256 + tid; cpa16(stg + idx * 16, a + (size_t)idx * 16); }
#pragma unroll
        for (int r = 0; r < 8; r++) { int idx = r * 256 + tid; cpa16(stg + 32768 + idx * 16, b + (size_t)idx * 16); }
        CP_COMMIT();
    }

    int wm = w >> 2, wn = w & 3;
    const int aRow = ((lane >> 3) & 1) * 8 + (lane & 7);
    const int aKh  = lane >> 4;
    const int bRow = (lane >> 4) * 8 + (lane & 7);
    const int bKh  = (lane >> 3) & 1;

    float d[4][4][4] = {};

    for (int c = 0; c < 16; c++) {
        int s = c & 1;
        CP_WAIT1();
        __syncthreads();
        u32 stA = sb + s * LSTAGE;
        u32 stB = stA + 32768;
#pragma unroll
        for (int k16 = 0; k16 < 4; k16++) {
            u32 aH[4][4], aL[4][4];
#pragma unroll
            for (int mi = 0; mi < 4; mi++) {
                u32 off = swz((u32)((wm * 64 + mi * 16 + aRow) * 128 + (k16 * 2 + aKh) * 16));
                ldsm4(aH[mi], stA + off);
                ldsm4(aL[mi], stA + 16384 + off);
            }
            u32 bH[2][4], bL[2][4];
#pragma unroll
            for (int bi = 0; bi < 2; bi++) {
                u32 off = swz((u32)((wn * 32 + bi * 16 + bRow) * 128 + (k16 * 2 + bKh) * 16));
                ldsm4(bH[bi], stB + off);
                ldsm4(bL[bi], stB + 16384 + off);
            }
#pragma unroll
            for (int mi = 0; mi < 4; mi++)
#pragma unroll
                for (int nj = 0; nj < 4; nj++) {
                    mma_bf16(d[mi][nj], aH[mi], &bH[nj >> 1][(nj & 1) * 2]);
                    mma_bf16(d[mi][nj], aH[mi], &bL[nj >> 1][(nj & 1) * 2]);
                    mma_bf16(d[mi][nj], aL[mi], &bH[nj >> 1][(nj & 1) * 2]);
                }
        }
        __syncthreads();
        if (c + 2 < 16) {
            u32 stg = sb + s * LSTAGE;
            const char* a = srcA + (size_t)(c + 2) * 32768;
            const char* b = srcB + (size_t)(c + 2) * 32768;
#pragma unroll
            for (int r = 0; r < 8; r++) { int idx = r * 256 + tid; cpa16(stg + idx * 16, a + (size_t)idx * 16); }
#pragma unroll
            for (int r = 0; r < 8; r++) { int idx = r * 256 + tid; cpa16(stg + 32768 + idx * 16, b + (size_t)idx * 16); }
        }
        CP_COMMIT();
    }

#pragma unroll
    for (int mi = 0; mi < 4; mi++)
#pragma unroll
        for (int nj = 0; nj < 4; nj++)
#pragma unroll
            for (int rh = 0; rh < 2; rh++) {
                int bl = wm * 64 + mi * 16 + (lane >> 2) + rh * 8;
                int b = mT * 128 + bl;
                int o = nOT * 128 + wn * 32 + nj * 8 + 2 * (lane & 3);
                float2 v = make_float2(d[mi][nj][rh * 2 + 0] + bout[o],
                                       d[mi][nj][rh * 2 + 1] + bout[o + 1]);
                *(float2*)&out[(size_t)b * 32768 + (size_t)t * 256 + o] = v;
            }
}

// ---------------- launch ----------------
extern "C" void kernel_launch(void* const* d_in, const int* in_sizes, int n_in,
                              void* d_out, int out_size)
{
    const float *enc = nullptr, *Wih = nullptr, *Whh = nullptr;
    const float *bih = nullptr, *bhh = nullptr, *Wout = nullptr, *bout = nullptr;
    for (int i = 0; i < n_in; i++) {
        int s = in_sizes[i];
        if      (s == 512 * 1024)  enc  = (const float*)d_in[i];
        else if (s == 4096 * 256)  Wih  = (const float*)d_in[i];
        else if (s == 4096 * 1024) Whh  = (const float*)d_in[i];
        else if (s == 4096)        { if (!bih) bih = (const float*)d_in[i]; else bhh = (const float*)d_in[i]; }
        else if (s == 256 * 1024)  Wout = (const float*)d_in[i];
        else if (s == 256)         bout = (const float*)d_in[i];
    }
    if (!enc || !Wih || !Whh || !bih || !bhh || !Wout || !bout) return;

    cudaFuncSetAttribute(prep_mma,     cudaFuncAttributeMaxDynamicSharedMemorySize, PREP_SMEM);
    cudaFuncSetAttribute(lstm_persist, cudaFuncAttributeMaxDynamicSharedMemorySize, LSTM_SMEM);
    cudaFuncSetAttribute(out_mma,      cudaFuncAttributeMaxDynamicSharedMemorySize, LSTM_SMEM);

    init_bar<<<3, 256>>>();
    prep_bias<<<512, 256>>>(Wih, bih, bhh, bout);
    conv_w0<<<dim3(16, 32), 128>>>(Whh);
    conv_wih<<<dim3(4, 32), 128>>>(Wih);
    conv_woutT<<<dim3(4, 16), 256>>>(Wout);
    conv_obf<<<dim3(16, 2), 128>>>(Wout);
    conv_h0<<<dim3(16, 4), 256>>>(enc);
    prep_mma<<<dim3(32, 16), 256, PREP_SMEM>>>(Whh);

    lstm_persist<<<dim3(4, 32), 256, LSTM_SMEM>>>();

    out_mma<<<dim3(4, 2, 128), 256, LSTM_SMEM>>>(bout, (float*)d_out);
    (void)out_size;
}